// round 1
// baseline (speedup 1.0000x reference)
#include <cuda_runtime.h>
#include <cuda_bf16.h>
#include <math_constants.h>

// Problem constants
#define BATCH 2
#define SEQ   2048
#define DIM_  1024
#define HEADS 16
#define HDIM  64
#define FUT   2
#define MROWS (BATCH * SEQ)        // 4096
#define QKVN  (3 * DIM_)           // 3072

// Scratch (allocation-free rule: __device__ globals)
__device__ float g_qkv[(size_t)MROWS * QKVN];   // 50.3 MB
__device__ float g_attn[(size_t)MROWS * DIM_];  // 16.8 MB

// ---------------------------------------------------------------------------
// Classic register-blocked SGEMM: C[M,N] = A[M,K] @ B[K,N] (+ bias[N])
// BM=BN=128, BK=8, 256 threads, 8x8 micro-tile per thread.
// Requires M%128==0, N%128==0, K%8==0 (true here).
// ---------------------------------------------------------------------------
#define BM 128
#define BN 128
#define BK 8
#define TM 8
#define TN 8

__global__ __launch_bounds__(256, 2)
void sgemm_kernel(const float* __restrict__ A, const float* __restrict__ B,
                  float* __restrict__ C, int M, int N, int K,
                  const float* __restrict__ bias)
{
    __shared__ float As[BK][BM];
    __shared__ float Bs[BK][BN];

    const int tid = threadIdx.x;
    const int block_row = blockIdx.y * BM;
    const int block_col = blockIdx.x * BN;

    // A tile loads: 128 rows x 8 k -> 256 float4 (each thread 1 float4, 4 k's)
    const int a_row = tid >> 1;            // 0..127
    const int a_col = (tid & 1) << 2;      // 0 or 4
    // B tile loads: 8 k x 128 cols -> 256 float4
    const int b_row = tid >> 5;            // 0..7
    const int b_col = (tid & 31) << 2;     // 0..124

    const int tx = tid & 15;               // 0..15 -> col group
    const int ty = tid >> 4;               // 0..15 -> row group

    float acc[TM][TN];
    #pragma unroll
    for (int i = 0; i < TM; i++)
        #pragma unroll
        for (int j = 0; j < TN; j++)
            acc[i][j] = 0.0f;

    const float* Aptr = A + (size_t)block_row * K;
    const float* Bptr = B + block_col;

    for (int k0 = 0; k0 < K; k0 += BK) {
        float4 av = *(const float4*)(Aptr + (size_t)a_row * K + k0 + a_col);
        As[a_col + 0][a_row] = av.x;
        As[a_col + 1][a_row] = av.y;
        As[a_col + 2][a_row] = av.z;
        As[a_col + 3][a_row] = av.w;

        float4 bv = *(const float4*)(Bptr + (size_t)(k0 + b_row) * N + b_col);
        *(float4*)&Bs[b_row][b_col] = bv;

        __syncthreads();

        #pragma unroll
        for (int k = 0; k < BK; k++) {
            float a_reg[TM], b_reg[TN];
            #pragma unroll
            for (int i = 0; i < TM; i++) a_reg[i] = As[k][ty * TM + i];
            #pragma unroll
            for (int j = 0; j < TN; j++) b_reg[j] = Bs[k][tx * TN + j];
            #pragma unroll
            for (int i = 0; i < TM; i++)
                #pragma unroll
                for (int j = 0; j < TN; j++)
                    acc[i][j] = fmaf(a_reg[i], b_reg[j], acc[i][j]);
        }
        __syncthreads();
    }

    #pragma unroll
    for (int i = 0; i < TM; i++) {
        const int row = block_row + ty * TM + i;
        #pragma unroll
        for (int j = 0; j < TN; j += 4) {
            const int col = block_col + tx * TN + j;
            float4 v;
            v.x = acc[i][j + 0];
            v.y = acc[i][j + 1];
            v.z = acc[i][j + 2];
            v.w = acc[i][j + 3];
            if (bias) {
                v.x += bias[col + 0];
                v.y += bias[col + 1];
                v.z += bias[col + 2];
                v.w += bias[col + 3];
            }
            *(float4*)(C + (size_t)row * N + col) = v;
        }
    }
}

// ---------------------------------------------------------------------------
// Banded attention: query (b,h,t) attends keys t..min(t+FUT, T-1).
// One warp per (m, h); lane covers dims {lane, lane+32} of hd=64.
// qkv layout: [m, 3*DIM]: q at c, k at DIM+c, v at 2*DIM+c, c = h*64+d.
// ---------------------------------------------------------------------------
__global__ void banded_attn_kernel(const float* __restrict__ qkv,
                                   float* __restrict__ attn_out)
{
    const int gwarp = (blockIdx.x * blockDim.x + threadIdx.x) >> 5;
    const int lane  = threadIdx.x & 31;
    const int total = MROWS * HEADS;
    if (gwarp >= total) return;

    const int h = gwarp % HEADS;
    const int m = gwarp / HEADS;
    const int t = m % SEQ;
    const int nk = min(FUT + 1, SEQ - t);   // valid keys: 1..3

    const size_t base = (size_t)m * QKVN + h * HDIM;
    const float q0 = qkv[base + lane];
    const float q1 = qkv[base + lane + 32];

    float s[FUT + 1];
    #pragma unroll
    for (int j = 0; j <= FUT; j++) {
        if (j < nk) {
            const size_t kb = (size_t)(m + j) * QKVN + DIM_ + h * HDIM;
            float d = q0 * qkv[kb + lane] + q1 * qkv[kb + lane + 32];
            #pragma unroll
            for (int off = 16; off > 0; off >>= 1)
                d += __shfl_xor_sync(0xffffffffu, d, off);
            s[j] = d * 0.125f;   // hd^-0.5 = 1/8
        } else {
            s[j] = -CUDART_INF_F;
        }
    }

    float mx = s[0];
    #pragma unroll
    for (int j = 1; j <= FUT; j++) mx = fmaxf(mx, s[j]);

    float e[FUT + 1];
    float denom = 0.0f;
    #pragma unroll
    for (int j = 0; j <= FUT; j++) {
        e[j] = (j < nk) ? __expf(s[j] - mx) : 0.0f;
        denom += e[j];
    }
    const float inv = 1.0f / denom;

    float o0 = 0.0f, o1 = 0.0f;
    #pragma unroll
    for (int j = 0; j <= FUT; j++) {
        if (j < nk) {
            const float p = e[j] * inv;
            const size_t vb = (size_t)(m + j) * QKVN + 2 * DIM_ + h * HDIM;
            o0 = fmaf(p, qkv[vb + lane], o0);
            o1 = fmaf(p, qkv[vb + lane + 32], o1);
        }
    }

    const size_t ob = (size_t)m * DIM_ + h * HDIM;
    attn_out[ob + lane] = o0;
    attn_out[ob + lane + 32] = o1;
}

// ---------------------------------------------------------------------------
// kernel_launch: 3 kernels, graph-capturable, allocation-free.
// ---------------------------------------------------------------------------
extern "C" void kernel_launch(void* const* d_in, const int* in_sizes, int n_in,
                              void* d_out, int out_size)
{
    const float* x      = (const float*)d_in[0];   // (2,2048,1024)
    const float* w_qkv  = (const float*)d_in[1];   // (1024,3072)
    const float* w_proj = (const float*)d_in[2];   // (1024,1024)
    const float* b_proj = (const float*)d_in[3];   // (1024,)
    float* out = (float*)d_out;                    // (2,2048,1024)

    float* qkv_ptr = nullptr;
    float* attn_ptr = nullptr;
    cudaGetSymbolAddress((void**)&qkv_ptr, g_qkv);
    cudaGetSymbolAddress((void**)&attn_ptr, g_attn);

    // 1) qkv = x @ w_qkv            (4096 x 3072 x 1024)
    {
        dim3 grid(QKVN / BN, MROWS / BM);
        sgemm_kernel<<<grid, 256>>>(x, w_qkv, qkv_ptr, MROWS, QKVN, DIM_, nullptr);
    }

    // 2) banded attention           (65536 warps)
    {
        const int total_warps = MROWS * HEADS;
        const int threads = 256;
        const int blocks = (total_warps * 32 + threads - 1) / threads;
        banded_attn_kernel<<<blocks, threads>>>(qkv_ptr, attn_ptr);
    }

    // 3) out = attn @ w_proj + b    (4096 x 1024 x 1024)
    {
        dim3 grid(DIM_ / BN, MROWS / BM);
        sgemm_kernel<<<grid, 256>>>(attn_ptr, w_proj, out, MROWS, DIM_, DIM_, b_proj);
    }
}

// round 3
// speedup vs baseline: 1.8346x; 1.8346x over previous
#include <cuda_runtime.h>
#include <cuda_bf16.h>
#include <mma.h>
#include <math_constants.h>
#include <cstdint>

using namespace nvcuda;

// ---------------------------------------------------------------------------
// Problem constants
// ---------------------------------------------------------------------------
#define BATCH 2
#define SEQ   2048
#define DIM_  1024
#define HEADS 16
#define HDIM  64
#define FUT   2
#define MROWS (BATCH * SEQ)   // 4096
#define QKVN  (3 * DIM_)      // 3072
#define KDIM  1024
#define KP    (3 * KDIM)      // 3072: [hi | lo | hi] x [hi | hi | lo] concat-K

// GEMM tiling
#define BM 128
#define BN 256
#define BK 32
#define NT (KP / BK)          // 96 k-tiles
#define PAD 8
#define LDSA (BK + PAD)       // 40 bf16 per smem row (80 B, 16B-aligned stride)
#define A_STAGE (BM * LDSA)   // elems
#define B_STAGE (BN * LDSA)
#define SMEM_BYTES ((2 * (A_STAGE + B_STAGE)) * 2)   // 61440 B

// ---------------------------------------------------------------------------
// Scratch (__device__ globals; allocation-free rule)
// ---------------------------------------------------------------------------
__device__ __nv_bfloat16 g_xs[(size_t)MROWS * KP];     // x split  [hi|lo|hi]
__device__ __nv_bfloat16 g_wqt[(size_t)QKVN * KP];     // w_qkv^T  [hi|hi|lo]
__device__ __nv_bfloat16 g_wpt[(size_t)DIM_ * KP];     // w_proj^T [hi|hi|lo]
__device__ float         g_qkv[(size_t)MROWS * QKVN];  // fp32 qkv
__device__ __nv_bfloat16 g_as[(size_t)MROWS * KP];     // attn out [hi|lo|hi]

// ---------------------------------------------------------------------------
// cp.async helpers
// ---------------------------------------------------------------------------
__device__ __forceinline__ void cp16(void* sdst, const void* gsrc) {
    uint32_t s = (uint32_t)__cvta_generic_to_shared(sdst);
    asm volatile("cp.async.cg.shared.global [%0], [%1], 16;\n" :: "r"(s), "l"(gsrc));
}
__device__ __forceinline__ void cp_commit() {
    asm volatile("cp.async.commit_group;\n" ::: "memory");
}
template <int N>
__device__ __forceinline__ void cp_wait() {
    asm volatile("cp.async.wait_group %0;\n" :: "n"(N) : "memory");
}

// ---------------------------------------------------------------------------
// WMMA GEMM: C[BMxBN tile] = A'[M,KP] @ B'[N,KP]^T (+bias), fp32 out.
// 256 threads = 8 warps of 64x64; double-buffered cp.async; bf16 HMMA.
// ---------------------------------------------------------------------------
__global__ __launch_bounds__(256, 1)
void gemm_wmma_kernel(const __nv_bfloat16* __restrict__ A,
                      const __nv_bfloat16* __restrict__ B,
                      float* __restrict__ C,
                      const float* __restrict__ bias, int ldN)
{
    extern __shared__ __align__(16) __nv_bfloat16 sm[];
    __nv_bfloat16* As = sm;                   // [2][BM][LDSA]
    __nv_bfloat16* Bs = sm + 2 * A_STAGE;     // [2][BN][LDSA]

    const int tid = threadIdx.x;
    const int wid = tid >> 5;
    const int lane = tid & 31;
    const int n0 = blockIdx.x * BN;
    const int m0 = blockIdx.y * BM;
    const int wm = (wid & 1) * 64;            // warp M offset in tile
    const int wn = (wid >> 1) * 64;           // warp N offset in tile

    wmma::fragment<wmma::accumulator, 16, 16, 16, float> c[4][4];

    if (bias) {
        // init accumulators from bias (replicated over rows)
        float* buf = (float*)sm + wid * 256;  // 16x16 staging per warp (8 KB)
        wmma::fragment<wmma::accumulator, 16, 16, 16, float> ci;
        #pragma unroll
        for (int j = 0; j < 4; j++) {
            for (int e = lane; e < 256; e += 32)
                buf[e] = bias[n0 + wn + j * 16 + (e & 15)];
            __syncwarp();
            wmma::load_matrix_sync(ci, buf, 16, wmma::mem_row_major);
            #pragma unroll
            for (int i = 0; i < 4; i++) c[i][j] = ci;
            __syncwarp();
        }
    } else {
        #pragma unroll
        for (int i = 0; i < 4; i++)
            #pragma unroll
            for (int j = 0; j < 4; j++)
                wmma::fill_fragment(c[i][j], 0.0f);
    }
    __syncthreads();

    auto load_tiles = [&](int kt, int s) {
        const int k0 = kt * BK;
        // A tile: 128 rows x 64 B = 512 x 16B chunks
        #pragma unroll
        for (int i = 0; i < 2; i++) {
            const int ch = tid + i * 256;
            const int row = ch >> 2, seg = ch & 3;
            cp16(As + s * A_STAGE + row * LDSA + seg * 8,
                 A + (size_t)(m0 + row) * KP + k0 + seg * 8);
        }
        // B tile: 256 rows x 64 B = 1024 x 16B chunks
        #pragma unroll
        for (int i = 0; i < 4; i++) {
            const int ch = tid + i * 256;
            const int row = ch >> 2, seg = ch & 3;
            cp16(Bs + s * B_STAGE + row * LDSA + seg * 8,
                 B + (size_t)(n0 + row) * KP + k0 + seg * 8);
        }
    };

    load_tiles(0, 0); cp_commit();
    load_tiles(1, 1); cp_commit();

    for (int kt = 0; kt < NT; kt++) {
        const int s = kt & 1;
        cp_wait<1>();
        __syncthreads();

        const __nv_bfloat16* as = As + s * A_STAGE + wm * LDSA;
        const __nv_bfloat16* bs = Bs + s * B_STAGE + wn * LDSA;
        #pragma unroll
        for (int kk = 0; kk < BK; kk += 16) {
            wmma::fragment<wmma::matrix_a, 16, 16, 16, __nv_bfloat16, wmma::row_major> af[4];
            wmma::fragment<wmma::matrix_b, 16, 16, 16, __nv_bfloat16, wmma::col_major> bf[4];
            #pragma unroll
            for (int i = 0; i < 4; i++)
                wmma::load_matrix_sync(af[i], as + i * 16 * LDSA + kk, LDSA);
            #pragma unroll
            for (int j = 0; j < 4; j++)
                wmma::load_matrix_sync(bf[j], bs + j * 16 * LDSA + kk, LDSA);
            #pragma unroll
            for (int i = 0; i < 4; i++)
                #pragma unroll
                for (int j = 0; j < 4; j++)
                    wmma::mma_sync(c[i][j], af[i], bf[j], c[i][j]);
        }
        __syncthreads();

        if (kt + 2 < NT) load_tiles(kt + 2, s);
        cp_commit();
    }

    // epilogue: direct fp32 stores (16x16 tiles, 64B row segments)
    #pragma unroll
    for (int i = 0; i < 4; i++)
        #pragma unroll
        for (int j = 0; j < 4; j++)
            wmma::store_matrix_sync(C + (size_t)(m0 + wm + i * 16) * ldN + n0 + wn + j * 16,
                                    c[i][j], ldN, wmma::mem_row_major);
}

// ---------------------------------------------------------------------------
// x -> [hi | lo | hi] bf16 concat
// ---------------------------------------------------------------------------
__global__ void split_x_kernel(const float* __restrict__ x,
                               __nv_bfloat16* __restrict__ dst)
{
    const int i = blockIdx.x * blockDim.x + threadIdx.x;
    if (i < MROWS * KDIM) {
        const int row = i >> 10, col = i & 1023;
        const float v = x[i];
        const __nv_bfloat16 h = __float2bfloat16(v);
        const __nv_bfloat16 l = __float2bfloat16(v - __bfloat162float(h));
        const size_t base = (size_t)row * KP + col;
        dst[base] = h;
        dst[base + KDIM] = l;
        dst[base + 2 * KDIM] = h;
    }
}

// W[K][N] fp32 -> Wt[N][KP] bf16 concat [hi | hi | lo]
__global__ void split_transpose_kernel(const float* __restrict__ W,
                                       __nv_bfloat16* __restrict__ Wt, int N)
{
    __shared__ float t[32][33];
    const int nb = blockIdx.x * 32;
    const int kb = blockIdx.y * 32;
    const int x = threadIdx.x, y = threadIdx.y;   // block (32, 8)
    #pragma unroll
    for (int i = 0; i < 32; i += 8)
        t[y + i][x] = W[(size_t)(kb + y + i) * N + nb + x];
    __syncthreads();
    #pragma unroll
    for (int i = 0; i < 32; i += 8) {
        const float v = t[x][y + i];              // = W[kb+x][nb+y+i]
        const __nv_bfloat16 h = __float2bfloat16(v);
        const __nv_bfloat16 l = __float2bfloat16(v - __bfloat162float(h));
        const size_t o = (size_t)(nb + y + i) * KP + kb + x;
        Wt[o] = h;
        Wt[o + KDIM] = h;
        Wt[o + 2 * KDIM] = l;
    }
}

// ---------------------------------------------------------------------------
// Banded attention: fp32 qkv in, bf16 [hi | lo | hi] concat out. Warp per (m,h).
// ---------------------------------------------------------------------------
__global__ void banded_attn_kernel(const float* __restrict__ qkv,
                                   __nv_bfloat16* __restrict__ out)
{
    const int gwarp = (blockIdx.x * blockDim.x + threadIdx.x) >> 5;
    const int lane  = threadIdx.x & 31;
    if (gwarp >= MROWS * HEADS) return;

    const int h = gwarp % HEADS;
    const int m = gwarp / HEADS;
    const int t = m % SEQ;
    const int nk = min(FUT + 1, SEQ - t);

    const size_t base = (size_t)m * QKVN + h * HDIM;
    const float q0 = qkv[base + lane];
    const float q1 = qkv[base + lane + 32];

    float s[FUT + 1];
    #pragma unroll
    for (int j = 0; j <= FUT; j++) {
        if (j < nk) {
            const size_t kb = (size_t)(m + j) * QKVN + DIM_ + h * HDIM;
            float d = q0 * qkv[kb + lane] + q1 * qkv[kb + lane + 32];
            #pragma unroll
            for (int off = 16; off > 0; off >>= 1)
                d += __shfl_xor_sync(0xffffffffu, d, off);
            s[j] = d * 0.125f;
        } else {
            s[j] = -CUDART_INF_F;
        }
    }

    float mx = s[0];
    #pragma unroll
    for (int j = 1; j <= FUT; j++) mx = fmaxf(mx, s[j]);

    float e[FUT + 1], denom = 0.0f;
    #pragma unroll
    for (int j = 0; j <= FUT; j++) {
        e[j] = (j < nk) ? __expf(s[j] - mx) : 0.0f;
        denom += e[j];
    }
    const float inv = 1.0f / denom;

    float o0 = 0.0f, o1 = 0.0f;
    #pragma unroll
    for (int j = 0; j <= FUT; j++) {
        if (j < nk) {
            const float p = e[j] * inv;
            const size_t vb = (size_t)(m + j) * QKVN + 2 * DIM_ + h * HDIM;
            o0 = fmaf(p, qkv[vb + lane], o0);
            o1 = fmaf(p, qkv[vb + lane + 32], o1);
        }
    }

    const int col = h * HDIM + lane;
    const size_t ob = (size_t)m * KP;
    const __nv_bfloat16 h0 = __float2bfloat16(o0);
    const __nv_bfloat16 h1 = __float2bfloat16(o1);
    out[ob + col]                   = h0;
    out[ob + col + 32]              = h1;
    out[ob + KDIM + col]            = __float2bfloat16(o0 - __bfloat162float(h0));
    out[ob + KDIM + col + 32]       = __float2bfloat16(o1 - __bfloat162float(h1));
    out[ob + 2 * KDIM + col]        = h0;
    out[ob + 2 * KDIM + col + 32]   = h1;
}

// ---------------------------------------------------------------------------
// kernel_launch
// ---------------------------------------------------------------------------
extern "C" void kernel_launch(void* const* d_in, const int* in_sizes, int n_in,
                              void* d_out, int out_size)
{
    const float* x      = (const float*)d_in[0];
    const float* w_qkv  = (const float*)d_in[1];
    const float* w_proj = (const float*)d_in[2];
    const float* b_proj = (const float*)d_in[3];
    float* out = (float*)d_out;

    __nv_bfloat16 *xs, *wqt, *wpt, *as;
    float* qkv;
    cudaGetSymbolAddress((void**)&xs, g_xs);
    cudaGetSymbolAddress((void**)&wqt, g_wqt);
    cudaGetSymbolAddress((void**)&wpt, g_wpt);
    cudaGetSymbolAddress((void**)&as, g_as);
    cudaGetSymbolAddress((void**)&qkv, g_qkv);

    static bool attr_done = false;
    if (!attr_done) {
        cudaFuncSetAttribute(gemm_wmma_kernel,
                             cudaFuncAttributeMaxDynamicSharedMemorySize, SMEM_BYTES);
        attr_done = true;
    }

    // 1) splits
    split_x_kernel<<<(MROWS * KDIM + 255) / 256, 256>>>(x, xs);
    split_transpose_kernel<<<dim3(QKVN / 32, KDIM / 32), dim3(32, 8)>>>(w_qkv, wqt, QKVN);
    split_transpose_kernel<<<dim3(DIM_ / 32, KDIM / 32), dim3(32, 8)>>>(w_proj, wpt, DIM_);

    // 2) qkv = x @ w_qkv  (M=4096, N=3072, K'=3072)
    gemm_wmma_kernel<<<dim3(QKVN / BN, MROWS / BM), 256, SMEM_BYTES>>>(
        xs, wqt, qkv, nullptr, QKVN);

    // 3) banded attention
    banded_attn_kernel<<<(MROWS * HEADS * 32 + 255) / 256, 256>>>(qkv, as);

    // 4) out = attn @ w_proj + b  (M=4096, N=1024, K'=3072)
    gemm_wmma_kernel<<<dim3(DIM_ / BN, MROWS / BM), 256, SMEM_BYTES>>>(
        as, wpt, out, b_proj, DIM_);
}

// round 4
// speedup vs baseline: 2.1379x; 1.1653x over previous
#include <cuda_runtime.h>
#include <cuda_bf16.h>
#include <mma.h>
#include <math_constants.h>
#include <cstdint>

using namespace nvcuda;

// ---------------------------------------------------------------------------
// Problem constants
// ---------------------------------------------------------------------------
#define BATCH 2
#define SEQ   2048
#define DIM_  1024
#define HEADS 16
#define HDIM  64
#define FUT   2
#define MROWS (BATCH * SEQ)   // 4096
#define QKVN  (3 * DIM_)      // 3072
#define KDIM  1024
#define KP    (3 * KDIM)      // 3072: [hi | lo | hi] x [hi | hi | lo] concat-K

// GEMM tiling
#define BM 128
#define BN 256
#define BK 64
#define NT (KP / BK)          // 48 k-tiles
#define NSTAGE 3
#define PAD 8
#define LDSA (BK + PAD)       // 72 bf16 per smem row
#define A_STAGE (BM * LDSA)   // elems
#define B_STAGE (BN * LDSA)
#define STAGE_ELEMS (A_STAGE + B_STAGE)
#define SMEM_BYTES (NSTAGE * STAGE_ELEMS * 2)   // 165888 B

// ---------------------------------------------------------------------------
// Scratch (__device__ globals; allocation-free rule)
// ---------------------------------------------------------------------------
__device__ __nv_bfloat16 g_xs[(size_t)MROWS * KP];     // x split  [hi|lo|hi]
__device__ __nv_bfloat16 g_wqt[(size_t)QKVN * KP];     // w_qkv^T  [hi|hi|lo]
__device__ __nv_bfloat16 g_wpt[(size_t)DIM_ * KP];     // w_proj^T [hi|hi|lo]
__device__ float         g_qkv[(size_t)MROWS * QKVN];  // fp32 qkv
__device__ __nv_bfloat16 g_as[(size_t)MROWS * KP];     // attn out [hi|lo|hi]

// ---------------------------------------------------------------------------
// cp.async helpers
// ---------------------------------------------------------------------------
__device__ __forceinline__ void cp16(void* sdst, const void* gsrc) {
    uint32_t s = (uint32_t)__cvta_generic_to_shared(sdst);
    asm volatile("cp.async.cg.shared.global [%0], [%1], 16;\n" :: "r"(s), "l"(gsrc));
}
__device__ __forceinline__ void cp_commit() {
    asm volatile("cp.async.commit_group;\n" ::: "memory");
}
template <int N>
__device__ __forceinline__ void cp_wait() {
    asm volatile("cp.async.wait_group %0;\n" :: "n"(N) : "memory");
}

// ---------------------------------------------------------------------------
// WMMA GEMM: C[BMxBN tile] = A'[M,KP] @ B'[N,KP]^T (+bias), fp32 out.
// 512 threads = 16 warps of 32x64; 3-stage cp.async; bf16 HMMA.
// ---------------------------------------------------------------------------
__global__ __launch_bounds__(512, 1)
void gemm_wmma_kernel(const __nv_bfloat16* __restrict__ A,
                      const __nv_bfloat16* __restrict__ B,
                      float* __restrict__ C,
                      const float* __restrict__ bias, int ldN)
{
    extern __shared__ __align__(16) __nv_bfloat16 sm[];

    const int tid = threadIdx.x;
    const int wid = tid >> 5;
    const int lane = tid & 31;
    const int n0 = blockIdx.x * BN;
    const int m0 = blockIdx.y * BM;
    const int wm = (wid & 3) * 32;            // warp M offset: 4 row groups
    const int wn = (wid >> 2) * 64;           // warp N offset: 4 col groups

    wmma::fragment<wmma::accumulator, 16, 16, 16, float> c[2][4];

    if (bias) {
        // init accumulators from bias (replicated over rows)
        float* buf = (float*)sm + wid * 256;  // 16x16 staging per warp (16 KB)
        wmma::fragment<wmma::accumulator, 16, 16, 16, float> ci;
        #pragma unroll
        for (int j = 0; j < 4; j++) {
            for (int e = lane; e < 256; e += 32)
                buf[e] = bias[n0 + wn + j * 16 + (e & 15)];
            __syncwarp();
            wmma::load_matrix_sync(ci, buf, 16, wmma::mem_row_major);
            c[0][j] = ci;
            c[1][j] = ci;
            __syncwarp();
        }
    } else {
        #pragma unroll
        for (int i = 0; i < 2; i++)
            #pragma unroll
            for (int j = 0; j < 4; j++)
                wmma::fill_fragment(c[i][j], 0.0f);
    }
    __syncthreads();

    auto load_tiles = [&](int kt, int s) {
        const int k0 = kt * BK;
        __nv_bfloat16* As = sm + s * STAGE_ELEMS;
        __nv_bfloat16* Bs = As + A_STAGE;
        // A tile: 128 rows x 128 B = 1024 x 16B chunks (2/thread)
        #pragma unroll
        for (int i = 0; i < 2; i++) {
            const int ch = tid + i * 512;
            const int row = ch >> 3, seg = ch & 7;
            cp16(As + row * LDSA + seg * 8,
                 A + (size_t)(m0 + row) * KP + k0 + seg * 8);
        }
        // B tile: 256 rows x 128 B = 2048 x 16B chunks (4/thread)
        #pragma unroll
        for (int i = 0; i < 4; i++) {
            const int ch = tid + i * 512;
            const int row = ch >> 3, seg = ch & 7;
            cp16(Bs + row * LDSA + seg * 8,
                 B + (size_t)(n0 + row) * KP + k0 + seg * 8);
        }
        cp_commit();
    };

    load_tiles(0, 0);
    load_tiles(1, 1);
    load_tiles(2, 2);

    for (int kt = 0; kt < NT; kt++) {
        const int s = kt % NSTAGE;
        cp_wait<2>();
        __syncthreads();

        const __nv_bfloat16* as = sm + s * STAGE_ELEMS + wm * LDSA;
        const __nv_bfloat16* bs = sm + s * STAGE_ELEMS + A_STAGE + wn * LDSA;
        #pragma unroll
        for (int kk = 0; kk < BK; kk += 16) {
            wmma::fragment<wmma::matrix_a, 16, 16, 16, __nv_bfloat16, wmma::row_major> af[2];
            wmma::load_matrix_sync(af[0], as + kk, LDSA);
            wmma::load_matrix_sync(af[1], as + 16 * LDSA + kk, LDSA);
            #pragma unroll
            for (int j = 0; j < 4; j++) {
                wmma::fragment<wmma::matrix_b, 16, 16, 16, __nv_bfloat16, wmma::col_major> bf;
                wmma::load_matrix_sync(bf, bs + j * 16 * LDSA + kk, LDSA);
                wmma::mma_sync(c[0][j], af[0], bf, c[0][j]);
                wmma::mma_sync(c[1][j], af[1], bf, c[1][j]);
            }
        }
        __syncthreads();

        if (kt + NSTAGE < NT) load_tiles(kt + NSTAGE, s);
    }

    // epilogue: direct fp32 stores
    #pragma unroll
    for (int i = 0; i < 2; i++)
        #pragma unroll
        for (int j = 0; j < 4; j++)
            wmma::store_matrix_sync(C + (size_t)(m0 + wm + i * 16) * ldN + n0 + wn + j * 16,
                                    c[i][j], ldN, wmma::mem_row_major);
}

// ---------------------------------------------------------------------------
// x -> [hi | lo | hi] bf16 concat
// ---------------------------------------------------------------------------
__global__ void split_x_kernel(const float* __restrict__ x,
                               __nv_bfloat16* __restrict__ dst)
{
    const int i = blockIdx.x * blockDim.x + threadIdx.x;
    if (i < MROWS * KDIM) {
        const int row = i >> 10, col = i & 1023;
        const float v = x[i];
        const __nv_bfloat16 h = __float2bfloat16(v);
        const __nv_bfloat16 l = __float2bfloat16(v - __bfloat162float(h));
        const size_t base = (size_t)row * KP + col;
        dst[base] = h;
        dst[base + KDIM] = l;
        dst[base + 2 * KDIM] = h;
    }
}

// W[K][N] fp32 -> Wt[N][KP] bf16 concat [hi | hi | lo]
__global__ void split_transpose_kernel(const float* __restrict__ W,
                                       __nv_bfloat16* __restrict__ Wt, int N)
{
    __shared__ float t[32][33];
    const int nb = blockIdx.x * 32;
    const int kb = blockIdx.y * 32;
    const int x = threadIdx.x, y = threadIdx.y;   // block (32, 8)
    #pragma unroll
    for (int i = 0; i < 32; i += 8)
        t[y + i][x] = W[(size_t)(kb + y + i) * N + nb + x];
    __syncthreads();
    #pragma unroll
    for (int i = 0; i < 32; i += 8) {
        const float v = t[x][y + i];              // = W[kb+x][nb+y+i]
        const __nv_bfloat16 h = __float2bfloat16(v);
        const __nv_bfloat16 l = __float2bfloat16(v - __bfloat162float(h));
        const size_t o = (size_t)(nb + y + i) * KP + kb + x;
        Wt[o] = h;
        Wt[o + KDIM] = h;
        Wt[o + 2 * KDIM] = l;
    }
}

// ---------------------------------------------------------------------------
// Banded attention: fp32 qkv in, bf16 [hi | lo | hi] concat out. Warp per (m,h).
// ---------------------------------------------------------------------------
__global__ void banded_attn_kernel(const float* __restrict__ qkv,
                                   __nv_bfloat16* __restrict__ out)
{
    const int gwarp = (blockIdx.x * blockDim.x + threadIdx.x) >> 5;
    const int lane  = threadIdx.x & 31;
    if (gwarp >= MROWS * HEADS) return;

    const int h = gwarp % HEADS;
    const int m = gwarp / HEADS;
    const int t = m % SEQ;
    const int nk = min(FUT + 1, SEQ - t);

    const size_t base = (size_t)m * QKVN + h * HDIM;
    const float q0 = qkv[base + lane];
    const float q1 = qkv[base + lane + 32];

    float s[FUT + 1];
    #pragma unroll
    for (int j = 0; j <= FUT; j++) {
        if (j < nk) {
            const size_t kb = (size_t)(m + j) * QKVN + DIM_ + h * HDIM;
            float d = q0 * qkv[kb + lane] + q1 * qkv[kb + lane + 32];
            #pragma unroll
            for (int off = 16; off > 0; off >>= 1)
                d += __shfl_xor_sync(0xffffffffu, d, off);
            s[j] = d * 0.125f;
        } else {
            s[j] = -CUDART_INF_F;
        }
    }

    float mx = s[0];
    #pragma unroll
    for (int j = 1; j <= FUT; j++) mx = fmaxf(mx, s[j]);

    float e[FUT + 1], denom = 0.0f;
    #pragma unroll
    for (int j = 0; j <= FUT; j++) {
        e[j] = (j < nk) ? __expf(s[j] - mx) : 0.0f;
        denom += e[j];
    }
    const float inv = 1.0f / denom;

    float o0 = 0.0f, o1 = 0.0f;
    #pragma unroll
    for (int j = 0; j <= FUT; j++) {
        if (j < nk) {
            const float p = e[j] * inv;
            const size_t vb = (size_t)(m + j) * QKVN + 2 * DIM_ + h * HDIM;
            o0 = fmaf(p, qkv[vb + lane], o0);
            o1 = fmaf(p, qkv[vb + lane + 32], o1);
        }
    }

    const int col = h * HDIM + lane;
    const size_t ob = (size_t)m * KP;
    const __nv_bfloat16 h0 = __float2bfloat16(o0);
    const __nv_bfloat16 h1 = __float2bfloat16(o1);
    out[ob + col]                   = h0;
    out[ob + col + 32]              = h1;
    out[ob + KDIM + col]            = __float2bfloat16(o0 - __bfloat162float(h0));
    out[ob + KDIM + col + 32]       = __float2bfloat16(o1 - __bfloat162float(h1));
    out[ob + 2 * KDIM + col]        = h0;
    out[ob + 2 * KDIM + col + 32]   = h1;
}

// ---------------------------------------------------------------------------
// kernel_launch
// ---------------------------------------------------------------------------
extern "C" void kernel_launch(void* const* d_in, const int* in_sizes, int n_in,
                              void* d_out, int out_size)
{
    const float* x      = (const float*)d_in[0];
    const float* w_qkv  = (const float*)d_in[1];
    const float* w_proj = (const float*)d_in[2];
    const float* b_proj = (const float*)d_in[3];
    float* out = (float*)d_out;

    __nv_bfloat16 *xs, *wqt, *wpt, *as;
    float* qkv;
    cudaGetSymbolAddress((void**)&xs, g_xs);
    cudaGetSymbolAddress((void**)&wqt, g_wqt);
    cudaGetSymbolAddress((void**)&wpt, g_wpt);
    cudaGetSymbolAddress((void**)&as, g_as);
    cudaGetSymbolAddress((void**)&qkv, g_qkv);

    static bool attr_done = false;
    if (!attr_done) {
        cudaFuncSetAttribute(gemm_wmma_kernel,
                             cudaFuncAttributeMaxDynamicSharedMemorySize, SMEM_BYTES);
        attr_done = true;
    }

    // 1) splits
    split_x_kernel<<<(MROWS * KDIM + 255) / 256, 256>>>(x, xs);
    split_transpose_kernel<<<dim3(QKVN / 32, KDIM / 32), dim3(32, 8)>>>(w_qkv, wqt, QKVN);
    split_transpose_kernel<<<dim3(DIM_ / 32, KDIM / 32), dim3(32, 8)>>>(w_proj, wpt, DIM_);

    // 2) qkv = x @ w_qkv  (M=4096, N=3072, K'=3072)
    gemm_wmma_kernel<<<dim3(QKVN / BN, MROWS / BM), 512, SMEM_BYTES>>>(
        xs, wqt, qkv, nullptr, QKVN);

    // 3) banded attention
    banded_attn_kernel<<<(MROWS * HEADS * 32 + 255) / 256, 256>>>(qkv, as);

    // 4) out = attn @ w_proj + b  (M=4096, N=1024, K'=3072)
    gemm_wmma_kernel<<<dim3(DIM_ / BN, MROWS / BM), 512, SMEM_BYTES>>>(
        as, wpt, out, b_proj, DIM_);
}

// round 5
// speedup vs baseline: 5.9508x; 2.7834x over previous
#include <cuda_runtime.h>
#include <cuda_fp16.h>
#include <math_constants.h>
#include <mma.h>
#include <cstdint>

using namespace nvcuda;

// ---------------------------------------------------------------------------
// Problem constants
// ---------------------------------------------------------------------------
#define BATCH 2
#define SEQ   2048
#define DIM_  1024
#define HEADS 16
#define HDIM  64
#define FUT   2
#define MROWS (BATCH * SEQ)   // 4096
#define QKVN  (3 * DIM_)      // 3072
#define KDIM  1024

// GEMM tiling
#define BM 128
#define BN 256
#define BK 64
#define NT (KDIM / BK)        // 16 k-tiles
#define NSTAGE 3
#define PAD 8
#define LDSA (BK + PAD)       // 72 halfs per smem row
#define A_STAGE (BM * LDSA)
#define B_STAGE (BN * LDSA)
#define STAGE_ELEMS (A_STAGE + B_STAGE)
#define SMEM_BYTES (NSTAGE * STAGE_ELEMS * 2)   // 165888 B

// ---------------------------------------------------------------------------
// Scratch (__device__ globals; allocation-free rule)
// ---------------------------------------------------------------------------
__device__ __half g_xh[(size_t)MROWS * KDIM];    // x fp16
__device__ __half g_wqt[(size_t)QKVN * KDIM];    // w_qkv^T fp16 [N][K]
__device__ __half g_wpt[(size_t)DIM_ * KDIM];    // w_proj^T fp16 [N][K]
__device__ float  g_qkv[(size_t)MROWS * QKVN];   // fp32 qkv
__device__ __half g_ah[(size_t)MROWS * KDIM];    // attention out fp16

// ---------------------------------------------------------------------------
// cp.async helpers
// ---------------------------------------------------------------------------
__device__ __forceinline__ void cp16(void* sdst, const void* gsrc) {
    uint32_t s = (uint32_t)__cvta_generic_to_shared(sdst);
    asm volatile("cp.async.cg.shared.global [%0], [%1], 16;\n" :: "r"(s), "l"(gsrc));
}
__device__ __forceinline__ void cp_commit() {
    asm volatile("cp.async.commit_group;\n" ::: "memory");
}
template <int N>
__device__ __forceinline__ void cp_wait() {
    asm volatile("cp.async.wait_group %0;\n" :: "n"(N) : "memory");
}

// ---------------------------------------------------------------------------
// fp16 WMMA GEMM: C[BMxBN tile] = A[M,K] @ B[N,K]^T (+bias), fp32 out.
// 512 threads = 16 warps of 32x64; 3-stage cp.async; ONE barrier per k-tile.
// ---------------------------------------------------------------------------
__global__ __launch_bounds__(512, 1)
void gemm_fp16_kernel(const __half* __restrict__ A,
                      const __half* __restrict__ B,
                      float* __restrict__ C,
                      const float* __restrict__ bias, int ldN)
{
    extern __shared__ __align__(16) __half sm[];

    const int tid = threadIdx.x;
    const int wid = tid >> 5;
    const int lane = tid & 31;
    const int n0 = blockIdx.x * BN;
    const int m0 = blockIdx.y * BM;
    const int wm = (wid & 3) * 32;            // warp M offset
    const int wn = (wid >> 2) * 64;           // warp N offset

    wmma::fragment<wmma::accumulator, 16, 16, 16, float> c[2][4];

    if (bias) {
        float* buf = (float*)sm + wid * 256;  // 16x16 staging per warp (16 KB)
        wmma::fragment<wmma::accumulator, 16, 16, 16, float> ci;
        #pragma unroll
        for (int j = 0; j < 4; j++) {
            for (int e = lane; e < 256; e += 32)
                buf[e] = bias[n0 + wn + j * 16 + (e & 15)];
            __syncwarp();
            wmma::load_matrix_sync(ci, buf, 16, wmma::mem_row_major);
            c[0][j] = ci;
            c[1][j] = ci;
            __syncwarp();
        }
    } else {
        #pragma unroll
        for (int i = 0; i < 2; i++)
            #pragma unroll
            for (int j = 0; j < 4; j++)
                wmma::fill_fragment(c[i][j], 0.0f);
    }
    __syncthreads();

    auto load_tiles = [&](int kt, int s) {
        const int k0 = kt * BK;
        __half* As = sm + s * STAGE_ELEMS;
        __half* Bs = As + A_STAGE;
        // A tile: 128 rows x 128 B = 1024 x 16B chunks (2/thread)
        #pragma unroll
        for (int i = 0; i < 2; i++) {
            const int ch = tid + i * 512;
            const int row = ch >> 3, seg = ch & 7;
            cp16(As + row * LDSA + seg * 8,
                 A + (size_t)(m0 + row) * KDIM + k0 + seg * 8);
        }
        // B tile: 256 rows x 128 B = 2048 x 16B chunks (4/thread)
        #pragma unroll
        for (int i = 0; i < 4; i++) {
            const int ch = tid + i * 512;
            const int row = ch >> 3, seg = ch & 7;
            cp16(Bs + row * LDSA + seg * 8,
                 B + (size_t)(n0 + row) * KDIM + k0 + seg * 8);
        }
        cp_commit();
    };

    load_tiles(0, 0);
    load_tiles(1, 1);

    #pragma unroll 1
    for (int kt = 0; kt < NT; kt++) {
        const int s = kt % NSTAGE;
        if (kt == NT - 1) cp_wait<0>(); else cp_wait<1>();
        __syncthreads();
        // Load into the stage consumed LAST iteration — freed by the barrier
        // above (all warps have finished computing kt-1). Single barrier/iter.
        if (kt + 2 < NT) load_tiles(kt + 2, (kt + 2) % NSTAGE);

        const __half* as = sm + s * STAGE_ELEMS + wm * LDSA;
        const __half* bs = sm + s * STAGE_ELEMS + A_STAGE + wn * LDSA;
        #pragma unroll
        for (int kk = 0; kk < BK; kk += 16) {
            wmma::fragment<wmma::matrix_a, 16, 16, 16, __half, wmma::row_major> af[2];
            wmma::load_matrix_sync(af[0], as + kk, LDSA);
            wmma::load_matrix_sync(af[1], as + 16 * LDSA + kk, LDSA);
            #pragma unroll
            for (int j = 0; j < 4; j++) {
                wmma::fragment<wmma::matrix_b, 16, 16, 16, __half, wmma::col_major> bf;
                wmma::load_matrix_sync(bf, bs + j * 16 * LDSA + kk, LDSA);
                wmma::mma_sync(c[0][j], af[0], bf, c[0][j]);
                wmma::mma_sync(c[1][j], af[1], bf, c[1][j]);
            }
        }
    }

    __syncthreads();
    // epilogue: direct fp32 stores
    #pragma unroll
    for (int i = 0; i < 2; i++)
        #pragma unroll
        for (int j = 0; j < 4; j++)
            wmma::store_matrix_sync(C + (size_t)(m0 + wm + i * 16) * ldN + n0 + wn + j * 16,
                                    c[i][j], ldN, wmma::mem_row_major);
}

// ---------------------------------------------------------------------------
// x fp32 -> fp16 (vectorized)
// ---------------------------------------------------------------------------
__global__ void convert_x_kernel(const float* __restrict__ x,
                                 __half* __restrict__ dst)
{
    const int i = blockIdx.x * blockDim.x + threadIdx.x;   // float4 index
    if (i < MROWS * KDIM / 4) {
        const float4 v = ((const float4*)x)[i];
        __half2* d = (__half2*)dst + i * 2;
        d[0] = __floats2half2_rn(v.x, v.y);
        d[1] = __floats2half2_rn(v.z, v.w);
    }
}

// W[K][N] fp32 -> Wt[N][K] fp16 (transpose)
__global__ void convert_transpose_kernel(const float* __restrict__ W,
                                         __half* __restrict__ Wt, int N)
{
    __shared__ float t[32][33];
    const int nb = blockIdx.x * 32;
    const int kb = blockIdx.y * 32;
    const int x = threadIdx.x, y = threadIdx.y;   // block (32, 8)
    #pragma unroll
    for (int i = 0; i < 32; i += 8)
        t[y + i][x] = W[(size_t)(kb + y + i) * N + nb + x];
    __syncthreads();
    #pragma unroll
    for (int i = 0; i < 32; i += 8)
        Wt[(size_t)(nb + y + i) * KDIM + kb + x] = __float2half_rn(t[x][y + i]);
}

// ---------------------------------------------------------------------------
// Banded attention: fp32 qkv in, fp16 out. One warp per (m, h).
// ---------------------------------------------------------------------------
__global__ void banded_attn_kernel(const float* __restrict__ qkv,
                                   __half* __restrict__ out)
{
    const int gwarp = (blockIdx.x * blockDim.x + threadIdx.x) >> 5;
    const int lane  = threadIdx.x & 31;
    if (gwarp >= MROWS * HEADS) return;

    const int h = gwarp % HEADS;
    const int m = gwarp / HEADS;
    const int t = m % SEQ;
    const int nk = min(FUT + 1, SEQ - t);

    const size_t base = (size_t)m * QKVN + h * HDIM;
    const float q0 = qkv[base + lane];
    const float q1 = qkv[base + lane + 32];

    float s[FUT + 1];
    #pragma unroll
    for (int j = 0; j <= FUT; j++) {
        if (j < nk) {
            const size_t kb = (size_t)(m + j) * QKVN + DIM_ + h * HDIM;
            float d = q0 * qkv[kb + lane] + q1 * qkv[kb + lane + 32];
            #pragma unroll
            for (int off = 16; off > 0; off >>= 1)
                d += __shfl_xor_sync(0xffffffffu, d, off);
            s[j] = d * 0.125f;
        } else {
            s[j] = -CUDART_INF_F;
        }
    }

    float mx = s[0];
    #pragma unroll
    for (int j = 1; j <= FUT; j++) mx = fmaxf(mx, s[j]);

    float e[FUT + 1], denom = 0.0f;
    #pragma unroll
    for (int j = 0; j <= FUT; j++) {
        e[j] = (j < nk) ? __expf(s[j] - mx) : 0.0f;
        denom += e[j];
    }
    const float inv = 1.0f / denom;

    float o0 = 0.0f, o1 = 0.0f;
    #pragma unroll
    for (int j = 0; j <= FUT; j++) {
        if (j < nk) {
            const float p = e[j] * inv;
            const size_t vb = (size_t)(m + j) * QKVN + 2 * DIM_ + h * HDIM;
            o0 = fmaf(p, qkv[vb + lane], o0);
            o1 = fmaf(p, qkv[vb + lane + 32], o1);
        }
    }

    const size_t ob = (size_t)m * KDIM + h * HDIM;
    out[ob + lane]      = __float2half_rn(o0);
    out[ob + lane + 32] = __float2half_rn(o1);
}

// ---------------------------------------------------------------------------
// kernel_launch
// ---------------------------------------------------------------------------
extern "C" void kernel_launch(void* const* d_in, const int* in_sizes, int n_in,
                              void* d_out, int out_size)
{
    const float* x      = (const float*)d_in[0];
    const float* w_qkv  = (const float*)d_in[1];
    const float* w_proj = (const float*)d_in[2];
    const float* b_proj = (const float*)d_in[3];
    float* out = (float*)d_out;

    __half *xh, *wqt, *wpt, *ah;
    float* qkv;
    cudaGetSymbolAddress((void**)&xh, g_xh);
    cudaGetSymbolAddress((void**)&wqt, g_wqt);
    cudaGetSymbolAddress((void**)&wpt, g_wpt);
    cudaGetSymbolAddress((void**)&ah, g_ah);
    cudaGetSymbolAddress((void**)&qkv, g_qkv);

    static bool attr_done = false;
    if (!attr_done) {
        cudaFuncSetAttribute(gemm_fp16_kernel,
                             cudaFuncAttributeMaxDynamicSharedMemorySize, SMEM_BYTES);
        attr_done = true;
    }

    // 1) converts
    convert_x_kernel<<<(MROWS * KDIM / 4 + 255) / 256, 256>>>(x, xh);
    convert_transpose_kernel<<<dim3(QKVN / 32, KDIM / 32), dim3(32, 8)>>>(w_qkv, wqt, QKVN);
    convert_transpose_kernel<<<dim3(DIM_ / 32, KDIM / 32), dim3(32, 8)>>>(w_proj, wpt, DIM_);

    // 2) qkv = x @ w_qkv  (M=4096, N=3072, K=1024)
    gemm_fp16_kernel<<<dim3(QKVN / BN, MROWS / BM), 512, SMEM_BYTES>>>(
        xh, wqt, qkv, nullptr, QKVN);

    // 3) banded attention
    banded_attn_kernel<<<(MROWS * HEADS * 32 + 255) / 256, 256>>>(qkv, ah);

    // 4) out = attn @ w_proj + b  (M=4096, N=1024, K=1024)
    gemm_fp16_kernel<<<dim3(DIM_ / BN, MROWS / BM), 512, SMEM_BYTES>>>(
        ah, wpt, out, b_proj, DIM_);
}

// round 6
// speedup vs baseline: 6.3098x; 1.0603x over previous
#include <cuda_runtime.h>
#include <cuda_fp16.h>
#include <math_constants.h>
#include <cstdint>

// ---------------------------------------------------------------------------
// Problem constants
// ---------------------------------------------------------------------------
#define BATCH 2
#define SEQ   2048
#define DIM_  1024
#define HEADS 16
#define HDIM  64
#define FUT   2
#define MROWS (BATCH * SEQ)   // 4096
#define QKVN  (3 * DIM_)      // 3072
#define KDIM  1024

// GEMM tiling
#define BM 128
#define BN 256
#define BK 64
#define NT (KDIM / BK)        // 16 k-tiles
#define NSTAGE 3
// smem: rows of 64 halfs (128B), 16B-chunk XOR swizzle (chunk ^= row&7)
#define A_ROW_BYTES 128
#define A_STAGE_BYTES (BM * A_ROW_BYTES)            // 16384
#define B_STAGE_BYTES (BN * A_ROW_BYTES)            // 32768
#define STAGE_BYTES (A_STAGE_BYTES + B_STAGE_BYTES) // 49152
#define SMEM_BYTES (NSTAGE * STAGE_BYTES)           // 147456

// ---------------------------------------------------------------------------
// Scratch (__device__ globals; allocation-free rule)
// ---------------------------------------------------------------------------
__device__ __half g_xh[(size_t)MROWS * KDIM];    // x fp16
__device__ __half g_wqt[(size_t)QKVN * KDIM];    // w_qkv^T fp16 [N][K]
__device__ __half g_wpt[(size_t)DIM_ * KDIM];    // w_proj^T fp16 [N][K]
__device__ float  g_qkv[(size_t)MROWS * QKVN];   // fp32 qkv
__device__ __half g_ah[(size_t)MROWS * KDIM];    // attention out fp16

// ---------------------------------------------------------------------------
// async-copy / mma helpers
// ---------------------------------------------------------------------------
__device__ __forceinline__ void cp16(uint32_t sdst, const void* gsrc) {
    asm volatile("cp.async.cg.shared.global [%0], [%1], 16;\n" :: "r"(sdst), "l"(gsrc));
}
__device__ __forceinline__ void cp_commit() {
    asm volatile("cp.async.commit_group;\n" ::: "memory");
}
template <int N>
__device__ __forceinline__ void cp_wait() {
    asm volatile("cp.async.wait_group %0;\n" :: "n"(N) : "memory");
}
__device__ __forceinline__ void ldsm4(uint32_t& d0, uint32_t& d1, uint32_t& d2,
                                      uint32_t& d3, uint32_t addr) {
    asm volatile("ldmatrix.sync.aligned.m8n8.x4.shared.b16 {%0,%1,%2,%3}, [%4];"
                 : "=r"(d0), "=r"(d1), "=r"(d2), "=r"(d3) : "r"(addr));
}
__device__ __forceinline__ void mma16816(float* c, const uint32_t* a,
                                         uint32_t b0, uint32_t b1) {
    asm volatile("mma.sync.aligned.m16n8k16.row.col.f32.f16.f16.f32 "
                 "{%0,%1,%2,%3}, {%4,%5,%6,%7}, {%8,%9}, {%0,%1,%2,%3};"
                 : "+f"(c[0]), "+f"(c[1]), "+f"(c[2]), "+f"(c[3])
                 : "r"(a[0]), "r"(a[1]), "r"(a[2]), "r"(a[3]), "r"(b0), "r"(b1));
}

// ---------------------------------------------------------------------------
// fp16 GEMM: C[BMxBN tile] = A[M,K] @ B[N,K]^T (+bias), fp32 out.
// 512 threads = 16 warps of 32x64; ldmatrix + mma.m16n8k16; swizzled smem.
// ---------------------------------------------------------------------------
__global__ __launch_bounds__(512, 1)
void gemm_fp16_kernel(const __half* __restrict__ A,
                      const __half* __restrict__ B,
                      float* __restrict__ C,
                      const float* __restrict__ bias, int ldN)
{
    extern __shared__ __align__(128) char sm[];
    const uint32_t sbase = (uint32_t)__cvta_generic_to_shared(sm);

    const int tid = threadIdx.x;
    const int wid = tid >> 5;
    const int lane = tid & 31;
    const int n0 = blockIdx.x * BN;
    const int m0 = blockIdx.y * BM;
    const int wm = (wid & 3) * 32;            // warp M offset
    const int wn = (wid >> 2) * 64;           // warp N offset

    float acc[2][8][4];
    #pragma unroll
    for (int i = 0; i < 2; i++)
        #pragma unroll
        for (int j = 0; j < 8; j++)
            #pragma unroll
            for (int e = 0; e < 4; e++)
                acc[i][j][e] = 0.0f;

    // ---- gmem -> smem loader with XOR swizzle ----
    auto load_tiles = [&](int kt, int s) {
        const int k0 = kt * BK;
        const uint32_t stA = sbase + s * STAGE_BYTES;
        const uint32_t stB = stA + A_STAGE_BYTES;
        // A: 128 rows x 8 chunks (16B) = 1024, 2/thread
        #pragma unroll
        for (int i = 0; i < 2; i++) {
            const int ch = tid + i * 512;
            const int row = ch >> 3, seg = ch & 7;
            const int ps = seg ^ (row & 7);
            cp16(stA + row * A_ROW_BYTES + ps * 16,
                 A + (size_t)(m0 + row) * KDIM + k0 + seg * 8);
        }
        // B: 256 rows x 8 chunks = 2048, 4/thread
        #pragma unroll
        for (int i = 0; i < 4; i++) {
            const int ch = tid + i * 512;
            const int row = ch >> 3, seg = ch & 7;
            const int ps = seg ^ (row & 7);
            cp16(stB + row * A_ROW_BYTES + ps * 16,
                 B + (size_t)(n0 + row) * KDIM + k0 + seg * 8);
        }
        cp_commit();
    };

    load_tiles(0, 0);
    load_tiles(1, 1);

    // per-thread ldmatrix address components
    const int lrow = lane & 15;               // row within 16-row tile
    const int lc = lane >> 4;                 // k-chunk half (0/1)
    const int l7 = lane & 7;                  // swizzle key (row & 7)

    #pragma unroll 1
    for (int kt = 0; kt < NT; kt++) {
        const int s = kt % NSTAGE;
        if (kt == NT - 1) cp_wait<0>(); else cp_wait<1>();
        __syncthreads();
        if (kt + 2 < NT) load_tiles(kt + 2, (kt + 2) % NSTAGE);

        const uint32_t stA = sbase + s * STAGE_BYTES;
        const uint32_t stB = stA + A_STAGE_BYTES;
        const uint32_t aRow = stA + (wm + lrow) * A_ROW_BYTES;
        const uint32_t bRow = stB + (wn + lrow) * A_ROW_BYTES;

        #pragma unroll
        for (int q = 0; q < 4; q++) {         // k16 steps within BK=64
            const uint32_t chunk = q * 2 + lc;
            const uint32_t poff = (chunk ^ l7) * 16;

            uint32_t a[2][4];
            ldsm4(a[0][0], a[0][1], a[0][2], a[0][3], aRow + poff);
            ldsm4(a[1][0], a[1][1], a[1][2], a[1][3], aRow + 16 * A_ROW_BYTES + poff);

            uint32_t b[4][4];
            #pragma unroll
            for (int ni = 0; ni < 4; ni++)
                ldsm4(b[ni][0], b[ni][1], b[ni][2], b[ni][3],
                      bRow + ni * 16 * A_ROW_BYTES + poff);

            #pragma unroll
            for (int mi = 0; mi < 2; mi++)
                #pragma unroll
                for (int j = 0; j < 8; j++) {
                    const int ni = j >> 1, hf = j & 1;
                    mma16816(acc[mi][j], a[mi], b[ni][hf], b[ni][hf + 2]);
                }
        }
    }

    // ---- epilogue: direct fp32 stores, bias fused ----
    const int erow = lane >> 2;               // 0..7
    const int ecol = (lane & 3) * 2;          // 0,2,4,6
    #pragma unroll
    for (int j = 0; j < 8; j++) {
        const int col = n0 + wn + j * 8 + ecol;
        float bx = 0.0f, by = 0.0f;
        if (bias) { bx = __ldg(bias + col); by = __ldg(bias + col + 1); }
        #pragma unroll
        for (int mi = 0; mi < 2; mi++) {
            const int r = m0 + wm + mi * 16 + erow;
            float2 v0 = make_float2(acc[mi][j][0] + bx, acc[mi][j][1] + by);
            float2 v1 = make_float2(acc[mi][j][2] + bx, acc[mi][j][3] + by);
            *(float2*)(C + (size_t)r * ldN + col) = v0;
            *(float2*)(C + (size_t)(r + 8) * ldN + col) = v1;
        }
    }
}

// ---------------------------------------------------------------------------
// x fp32 -> fp16 (vectorized)
// ---------------------------------------------------------------------------
__global__ void convert_x_kernel(const float* __restrict__ x,
                                 __half* __restrict__ dst)
{
    const int i = blockIdx.x * blockDim.x + threadIdx.x;   // float4 index
    if (i < MROWS * KDIM / 4) {
        const float4 v = ((const float4*)x)[i];
        __half2* d = (__half2*)dst + i * 2;
        d[0] = __floats2half2_rn(v.x, v.y);
        d[1] = __floats2half2_rn(v.z, v.w);
    }
}

// W[K][N] fp32 -> Wt[N][K] fp16 (transpose)
__global__ void convert_transpose_kernel(const float* __restrict__ W,
                                         __half* __restrict__ Wt, int N)
{
    __shared__ float t[32][33];
    const int nb = blockIdx.x * 32;
    const int kb = blockIdx.y * 32;
    const int x = threadIdx.x, y = threadIdx.y;   // block (32, 8)
    #pragma unroll
    for (int i = 0; i < 32; i += 8)
        t[y + i][x] = W[(size_t)(kb + y + i) * N + nb + x];
    __syncthreads();
    #pragma unroll
    for (int i = 0; i < 32; i += 8)
        Wt[(size_t)(nb + y + i) * KDIM + kb + x] = __float2half_rn(t[x][y + i]);
}

// ---------------------------------------------------------------------------
// Banded attention: fp32 qkv in, fp16 out. One warp per (m, h).
// ---------------------------------------------------------------------------
__global__ void banded_attn_kernel(const float* __restrict__ qkv,
                                   __half* __restrict__ out)
{
    const int gwarp = (blockIdx.x * blockDim.x + threadIdx.x) >> 5;
    const int lane  = threadIdx.x & 31;
    if (gwarp >= MROWS * HEADS) return;

    const int h = gwarp % HEADS;
    const int m = gwarp / HEADS;
    const int t = m % SEQ;
    const int nk = min(FUT + 1, SEQ - t);

    const size_t base = (size_t)m * QKVN + h * HDIM;
    const float q0 = qkv[base + lane];
    const float q1 = qkv[base + lane + 32];

    float s[FUT + 1];
    #pragma unroll
    for (int j = 0; j <= FUT; j++) {
        if (j < nk) {
            const size_t kb = (size_t)(m + j) * QKVN + DIM_ + h * HDIM;
            float d = q0 * qkv[kb + lane] + q1 * qkv[kb + lane + 32];
            #pragma unroll
            for (int off = 16; off > 0; off >>= 1)
                d += __shfl_xor_sync(0xffffffffu, d, off);
            s[j] = d * 0.125f;
        } else {
            s[j] = -CUDART_INF_F;
        }
    }

    float mx = s[0];
    #pragma unroll
    for (int j = 1; j <= FUT; j++) mx = fmaxf(mx, s[j]);

    float e[FUT + 1], denom = 0.0f;
    #pragma unroll
    for (int j = 0; j <= FUT; j++) {
        e[j] = (j < nk) ? __expf(s[j] - mx) : 0.0f;
        denom += e[j];
    }
    const float inv = 1.0f / denom;

    float o0 = 0.0f, o1 = 0.0f;
    #pragma unroll
    for (int j = 0; j <= FUT; j++) {
        if (j < nk) {
            const float p = e[j] * inv;
            const size_t vb = (size_t)(m + j) * QKVN + 2 * DIM_ + h * HDIM;
            o0 = fmaf(p, qkv[vb + lane], o0);
            o1 = fmaf(p, qkv[vb + lane + 32], o1);
        }
    }

    const size_t ob = (size_t)m * KDIM + h * HDIM;
    out[ob + lane]      = __float2half_rn(o0);
    out[ob + lane + 32] = __float2half_rn(o1);
}

// ---------------------------------------------------------------------------
// kernel_launch
// ---------------------------------------------------------------------------
extern "C" void kernel_launch(void* const* d_in, const int* in_sizes, int n_in,
                              void* d_out, int out_size)
{
    const float* x      = (const float*)d_in[0];
    const float* w_qkv  = (const float*)d_in[1];
    const float* w_proj = (const float*)d_in[2];
    const float* b_proj = (const float*)d_in[3];
    float* out = (float*)d_out;

    __half *xh, *wqt, *wpt, *ah;
    float* qkv;
    cudaGetSymbolAddress((void**)&xh, g_xh);
    cudaGetSymbolAddress((void**)&wqt, g_wqt);
    cudaGetSymbolAddress((void**)&wpt, g_wpt);
    cudaGetSymbolAddress((void**)&ah, g_ah);
    cudaGetSymbolAddress((void**)&qkv, g_qkv);

    static bool attr_done = false;
    if (!attr_done) {
        cudaFuncSetAttribute(gemm_fp16_kernel,
                             cudaFuncAttributeMaxDynamicSharedMemorySize, SMEM_BYTES);
        attr_done = true;
    }

    // 1) converts
    convert_x_kernel<<<(MROWS * KDIM / 4 + 255) / 256, 256>>>(x, xh);
    convert_transpose_kernel<<<dim3(QKVN / 32, KDIM / 32), dim3(32, 8)>>>(w_qkv, wqt, QKVN);
    convert_transpose_kernel<<<dim3(DIM_ / 32, KDIM / 32), dim3(32, 8)>>>(w_proj, wpt, DIM_);

    // 2) qkv = x @ w_qkv  (M=4096, N=3072, K=1024)
    gemm_fp16_kernel<<<dim3(QKVN / BN, MROWS / BM), 512, SMEM_BYTES>>>(
        xh, wqt, qkv, nullptr, QKVN);

    // 3) banded attention
    banded_attn_kernel<<<(MROWS * HEADS * 32 + 255) / 256, 256>>>(qkv, ah);

    // 4) out = attn @ w_proj + b  (M=4096, N=1024, K=1024)
    gemm_fp16_kernel<<<dim3(DIM_ / BN, MROWS / BM), 512, SMEM_BYTES>>>(
        ah, wpt, out, b_proj, DIM_);
}

// round 7
// speedup vs baseline: 6.4375x; 1.0202x over previous
#include <cuda_runtime.h>
#include <cuda_fp16.h>
#include <math_constants.h>
#include <cstdint>

// ---------------------------------------------------------------------------
// Problem constants
// ---------------------------------------------------------------------------
#define BATCH 2
#define SEQ   2048
#define DIM_  1024
#define HEADS 16
#define HDIM  64
#define FUT   2
#define MROWS (BATCH * SEQ)   // 4096
#define QKVN  (3 * DIM_)      // 3072
#define KDIM  1024

// GEMM tiling: 128x128 CTA tile, 8 warps of 32x64, 2 CTAs/SM
#define BM 128
#define BN 128
#define BK 64
#define NT (KDIM / BK)        // 16 k-tiles
#define NSTAGE 3
#define ROW_BYTES 128         // 64 halfs per row
#define A_STAGE_BYTES (BM * ROW_BYTES)              // 16384
#define B_STAGE_BYTES (BN * ROW_BYTES)              // 16384
#define STAGE_BYTES (A_STAGE_BYTES + B_STAGE_BYTES) // 32768
#define SMEM_BYTES (NSTAGE * STAGE_BYTES)           // 98304

// ---------------------------------------------------------------------------
// Scratch (__device__ globals; allocation-free rule)
// ---------------------------------------------------------------------------
__device__ __half g_xh[(size_t)MROWS * KDIM];    // x fp16
__device__ __half g_wqt[(size_t)QKVN * KDIM];    // w_qkv^T fp16 [N][K]
__device__ __half g_wpt[(size_t)DIM_ * KDIM];    // w_proj^T fp16 [N][K]
__device__ float  g_qkv[(size_t)MROWS * QKVN];   // fp32 qkv
__device__ __half g_ah[(size_t)MROWS * KDIM];    // attention out fp16

// ---------------------------------------------------------------------------
// async-copy / mma helpers
// ---------------------------------------------------------------------------
__device__ __forceinline__ void cp16(uint32_t sdst, const void* gsrc) {
    asm volatile("cp.async.cg.shared.global [%0], [%1], 16;\n" :: "r"(sdst), "l"(gsrc));
}
__device__ __forceinline__ void cp_commit() {
    asm volatile("cp.async.commit_group;\n" ::: "memory");
}
template <int N>
__device__ __forceinline__ void cp_wait() {
    asm volatile("cp.async.wait_group %0;\n" :: "n"(N) : "memory");
}
__device__ __forceinline__ void ldsm4(uint32_t& d0, uint32_t& d1, uint32_t& d2,
                                      uint32_t& d3, uint32_t addr) {
    asm volatile("ldmatrix.sync.aligned.m8n8.x4.shared.b16 {%0,%1,%2,%3}, [%4];"
                 : "=r"(d0), "=r"(d1), "=r"(d2), "=r"(d3) : "r"(addr));
}
__device__ __forceinline__ void mma16816(float* c, const uint32_t* a,
                                         uint32_t b0, uint32_t b1) {
    asm volatile("mma.sync.aligned.m16n8k16.row.col.f32.f16.f16.f32 "
                 "{%0,%1,%2,%3}, {%4,%5,%6,%7}, {%8,%9}, {%0,%1,%2,%3};"
                 : "+f"(c[0]), "+f"(c[1]), "+f"(c[2]), "+f"(c[3])
                 : "r"(a[0]), "r"(a[1]), "r"(a[2]), "r"(a[3]), "r"(b0), "r"(b1));
}

// ---------------------------------------------------------------------------
// fp16 GEMM: C[BMxBN tile] = A[M,K] @ B[N,K]^T (+bias), fp32 out.
// 256 threads = 8 warps of 32x64; 2 CTAs/SM for cross-CTA latency hiding.
// ---------------------------------------------------------------------------
__global__ __launch_bounds__(256, 2)
void gemm_fp16_kernel(const __half* __restrict__ A,
                      const __half* __restrict__ B,
                      float* __restrict__ C,
                      const float* __restrict__ bias, int ldN)
{
    extern __shared__ __align__(128) char sm[];
    const uint32_t sbase = (uint32_t)__cvta_generic_to_shared(sm);

    const int tid = threadIdx.x;
    const int wid = tid >> 5;
    const int lane = tid & 31;
    const int n0 = blockIdx.x * BN;
    const int m0 = blockIdx.y * BM;
    const int wm = (wid & 3) * 32;            // warp M offset (4 groups)
    const int wn = (wid >> 2) * 64;           // warp N offset (2 groups)

    float acc[2][8][4];
    #pragma unroll
    for (int i = 0; i < 2; i++)
        #pragma unroll
        for (int j = 0; j < 8; j++)
            #pragma unroll
            for (int e = 0; e < 4; e++)
                acc[i][j][e] = 0.0f;

    // ---- gmem -> smem loader with XOR swizzle (16B chunk ^= row&7) ----
    auto load_tiles = [&](int kt, int s) {
        const int k0 = kt * BK;
        const uint32_t stA = sbase + s * STAGE_BYTES;
        const uint32_t stB = stA + A_STAGE_BYTES;
        // A: 128 rows x 8 chunks = 1024, 4/thread
        #pragma unroll
        for (int i = 0; i < 4; i++) {
            const int ch = tid + i * 256;
            const int row = ch >> 3, seg = ch & 7;
            const int ps = seg ^ (row & 7);
            cp16(stA + row * ROW_BYTES + ps * 16,
                 A + (size_t)(m0 + row) * KDIM + k0 + seg * 8);
        }
        // B: 128 rows x 8 chunks = 1024, 4/thread
        #pragma unroll
        for (int i = 0; i < 4; i++) {
            const int ch = tid + i * 256;
            const int row = ch >> 3, seg = ch & 7;
            const int ps = seg ^ (row & 7);
            cp16(stB + row * ROW_BYTES + ps * 16,
                 B + (size_t)(n0 + row) * KDIM + k0 + seg * 8);
        }
        cp_commit();
    };

    load_tiles(0, 0);
    load_tiles(1, 1);

    // per-thread ldmatrix address components
    const int lrow = lane & 15;               // row within 16-row tile
    const int lc = lane >> 4;                 // k-chunk half (0/1)
    const int l7 = lane & 7;                  // swizzle key

    #pragma unroll 1
    for (int kt = 0; kt < NT; kt++) {
        const int s = kt % NSTAGE;
        if (kt == NT - 1) cp_wait<0>(); else cp_wait<1>();
        __syncthreads();
        if (kt + 2 < NT) load_tiles(kt + 2, (kt + 2) % NSTAGE);

        const uint32_t stA = sbase + s * STAGE_BYTES;
        const uint32_t stB = stA + A_STAGE_BYTES;
        const uint32_t aRow = stA + (wm + lrow) * ROW_BYTES;
        const uint32_t bRow = stB + (wn + lrow) * ROW_BYTES;

        #pragma unroll
        for (int q = 0; q < 4; q++) {         // k16 steps within BK=64
            const uint32_t chunk = q * 2 + lc;
            const uint32_t poff = (chunk ^ l7) * 16;

            uint32_t a[2][4];
            ldsm4(a[0][0], a[0][1], a[0][2], a[0][3], aRow + poff);
            ldsm4(a[1][0], a[1][1], a[1][2], a[1][3], aRow + 16 * ROW_BYTES + poff);

            uint32_t b[4][4];
            #pragma unroll
            for (int ni = 0; ni < 4; ni++)
                ldsm4(b[ni][0], b[ni][1], b[ni][2], b[ni][3],
                      bRow + ni * 16 * ROW_BYTES + poff);

            #pragma unroll
            for (int mi = 0; mi < 2; mi++)
                #pragma unroll
                for (int j = 0; j < 8; j++) {
                    const int ni = j >> 1, hf = j & 1;
                    mma16816(acc[mi][j], a[mi], b[ni][hf], b[ni][hf + 2]);
                }
        }
    }

    // ---- epilogue: direct fp32 stores, bias fused ----
    const int erow = lane >> 2;               // 0..7
    const int ecol = (lane & 3) * 2;          // 0,2,4,6
    #pragma unroll
    for (int j = 0; j < 8; j++) {
        const int col = n0 + wn + j * 8 + ecol;
        float bx = 0.0f, by = 0.0f;
        if (bias) { bx = __ldg(bias + col); by = __ldg(bias + col + 1); }
        #pragma unroll
        for (int mi = 0; mi < 2; mi++) {
            const int r = m0 + wm + mi * 16 + erow;
            float2 v0 = make_float2(acc[mi][j][0] + bx, acc[mi][j][1] + by);
            float2 v1 = make_float2(acc[mi][j][2] + bx, acc[mi][j][3] + by);
            *(float2*)(C + (size_t)r * ldN + col) = v0;
            *(float2*)(C + (size_t)(r + 8) * ldN + col) = v1;
        }
    }
}

// ---------------------------------------------------------------------------
// x fp32 -> fp16 (vectorized)
// ---------------------------------------------------------------------------
__global__ void convert_x_kernel(const float* __restrict__ x,
                                 __half* __restrict__ dst)
{
    const int i = blockIdx.x * blockDim.x + threadIdx.x;   // float4 index
    if (i < MROWS * KDIM / 4) {
        const float4 v = ((const float4*)x)[i];
        __half2* d = (__half2*)dst + i * 2;
        d[0] = __floats2half2_rn(v.x, v.y);
        d[1] = __floats2half2_rn(v.z, v.w);
    }
}

// W[K][N] fp32 -> Wt[N][K] fp16 (transpose)
__global__ void convert_transpose_kernel(const float* __restrict__ W,
                                         __half* __restrict__ Wt, int N)
{
    __shared__ float t[32][33];
    const int nb = blockIdx.x * 32;
    const int kb = blockIdx.y * 32;
    const int x = threadIdx.x, y = threadIdx.y;   // block (32, 8)
    #pragma unroll
    for (int i = 0; i < 32; i += 8)
        t[y + i][x] = W[(size_t)(kb + y + i) * N + nb + x];
    __syncthreads();
    #pragma unroll
    for (int i = 0; i < 32; i += 8)
        Wt[(size_t)(nb + y + i) * KDIM + kb + x] = __float2half_rn(t[x][y + i]);
}

// ---------------------------------------------------------------------------
// Banded attention: fp32 qkv in, fp16 out. One warp per (m, h).
// ---------------------------------------------------------------------------
__global__ void banded_attn_kernel(const float* __restrict__ qkv,
                                   __half* __restrict__ out)
{
    const int gwarp = (blockIdx.x * blockDim.x + threadIdx.x) >> 5;
    const int lane  = threadIdx.x & 31;
    if (gwarp >= MROWS * HEADS) return;

    const int h = gwarp % HEADS;
    const int m = gwarp / HEADS;
    const int t = m % SEQ;
    const int nk = min(FUT + 1, SEQ - t);

    const size_t base = (size_t)m * QKVN + h * HDIM;
    const float q0 = qkv[base + lane];
    const float q1 = qkv[base + lane + 32];

    float s[FUT + 1];
    #pragma unroll
    for (int j = 0; j <= FUT; j++) {
        if (j < nk) {
            const size_t kb = (size_t)(m + j) * QKVN + DIM_ + h * HDIM;
            float d = q0 * qkv[kb + lane] + q1 * qkv[kb + lane + 32];
            #pragma unroll
            for (int off = 16; off > 0; off >>= 1)
                d += __shfl_xor_sync(0xffffffffu, d, off);
            s[j] = d * 0.125f;
        } else {
            s[j] = -CUDART_INF_F;
        }
    }

    float mx = s[0];
    #pragma unroll
    for (int j = 1; j <= FUT; j++) mx = fmaxf(mx, s[j]);

    float e[FUT + 1], denom = 0.0f;
    #pragma unroll
    for (int j = 0; j <= FUT; j++) {
        e[j] = (j < nk) ? __expf(s[j] - mx) : 0.0f;
        denom += e[j];
    }
    const float inv = 1.0f / denom;

    float o0 = 0.0f, o1 = 0.0f;
    #pragma unroll
    for (int j = 0; j <= FUT; j++) {
        if (j < nk) {
            const float p = e[j] * inv;
            const size_t vb = (size_t)(m + j) * QKVN + 2 * DIM_ + h * HDIM;
            o0 = fmaf(p, qkv[vb + lane], o0);
            o1 = fmaf(p, qkv[vb + lane + 32], o1);
        }
    }

    const size_t ob = (size_t)m * KDIM + h * HDIM;
    out[ob + lane]      = __float2half_rn(o0);
    out[ob + lane + 32] = __float2half_rn(o1);
}

// ---------------------------------------------------------------------------
// kernel_launch
// ---------------------------------------------------------------------------
extern "C" void kernel_launch(void* const* d_in, const int* in_sizes, int n_in,
                              void* d_out, int out_size)
{
    const float* x      = (const float*)d_in[0];
    const float* w_qkv  = (const float*)d_in[1];
    const float* w_proj = (const float*)d_in[2];
    const float* b_proj = (const float*)d_in[3];
    float* out = (float*)d_out;

    __half *xh, *wqt, *wpt, *ah;
    float* qkv;
    cudaGetSymbolAddress((void**)&xh, g_xh);
    cudaGetSymbolAddress((void**)&wqt, g_wqt);
    cudaGetSymbolAddress((void**)&wpt, g_wpt);
    cudaGetSymbolAddress((void**)&ah, g_ah);
    cudaGetSymbolAddress((void**)&qkv, g_qkv);

    static bool attr_done = false;
    if (!attr_done) {
        cudaFuncSetAttribute(gemm_fp16_kernel,
                             cudaFuncAttributeMaxDynamicSharedMemorySize, SMEM_BYTES);
        attr_done = true;
    }

    // 1) converts
    convert_x_kernel<<<(MROWS * KDIM / 4 + 255) / 256, 256>>>(x, xh);
    convert_transpose_kernel<<<dim3(QKVN / 32, KDIM / 32), dim3(32, 8)>>>(w_qkv, wqt, QKVN);
    convert_transpose_kernel<<<dim3(DIM_ / 32, KDIM / 32), dim3(32, 8)>>>(w_proj, wpt, DIM_);

    // 2) qkv = x @ w_qkv  (M=4096, N=3072, K=1024)
    gemm_fp16_kernel<<<dim3(QKVN / BN, MROWS / BM), 256, SMEM_BYTES>>>(
        xh, wqt, qkv, nullptr, QKVN);

    // 3) banded attention
    banded_attn_kernel<<<(MROWS * HEADS * 32 + 255) / 256, 256>>>(qkv, ah);

    // 4) out = attn @ w_proj + b  (M=4096, N=1024, K=1024)
    gemm_fp16_kernel<<<dim3(DIM_ / BN, MROWS / BM), 256, SMEM_BYTES>>>(
        ah, wpt, out, b_proj, DIM_);
}